// round 15
// baseline (speedup 1.0000x reference)
#include <cuda_runtime.h>
#include <math.h>

#define BB       4096
#define SRC_LEN  128
#define IN_DIM   16
#define HH       64
#define SEQ_LEN  100
#define MEAN_DIM 4
#define COV_DIM  10

#define THREADS1 128             // 4 warps = 2 groups per CTA
#define NGROUP   2
#define EPG      16              // batch elements per group (8 e-pairs)
#define GRID1    128             // 128 * 2 * 16 = 4096
#define MEANS_OFF 0
#define COVS_OFF  (BB*SEQ_LEN*MEAN_DIM)

#define WSTRIDE   68             // padded row stride (floats) for Whh rows
#define WISTRIDE  20             // padded row stride for Wih rows
#define OWSTRIDE  68             // padded row stride for outW rows

typedef unsigned long long ull;

// decoder output scratch [B][SEQ_LEN][IN_DIM]
__device__ __align__(16) float g_dec[BB*SEQ_LEN*IN_DIM];

// group barrier: named barrier (1+g), 64 threads
#define PBAR(g) asm volatile("bar.sync %0, 64;" :: "r"(1+(g)) : "memory")

// ---------------------------------------------------------------------------
// f32x2 packed helpers
// ---------------------------------------------------------------------------
__device__ __forceinline__ ull pack2(float x, float y){
    ull r; asm("mov.b64 %0,{%1,%2};" : "=l"(r) : "f"(x), "f"(y)); return r;
}
__device__ __forceinline__ float2 unpack2(ull v){
    float2 r; asm("mov.b64 {%0,%1},%2;" : "=f"(r.x), "=f"(r.y) : "l"(v)); return r;
}
__device__ __forceinline__ ull fma2(ull a, ull b, ull c){
    ull d; asm("fma.rn.f32x2 %0,%1,%2,%3;" : "=l"(d) : "l"(a), "l"(b), "l"(c)); return d;
}
__device__ __forceinline__ float tanhapx(float x){
    float y; asm("tanh.approx.f32 %0,%1;" : "=f"(y) : "f"(x)); return y;
}
// sigmoid(x) = 0.5 + 0.5*tanh(0.5x)  (1 MUFU)
__device__ __forceinline__ float sigm(float x){
    return fmaf(tanhapx(0.5f*x), 0.5f, 0.5f);
}

// ---------------------------------------------------------------------------
// SMEM (~90 KB dynamic)
// h layout per group: h2[g][buf][k*8 + p]  (k = h-row, p = e-pair 0..7)
// x layout per group: x2[g][buf][d*8 + p]
// ---------------------------------------------------------------------------
struct Smem {
    __align__(16) float wT [192*WSTRIDE];     // Whh rows, padded stride
    __align__(16) float wiT[192*WISTRIDE];    // Wih rows, padded stride
    __align__(16) float outw[16*OWSTRIDE];    // outW rows, padded stride
    __align__(16) ull   h2[NGROUP][2][HH*8];  // double-buffered h state
    __align__(16) ull   x2[NGROUP][2][IN_DIM*8];
};

// ---------------------------------------------------------------------------
// Gate accumulation for ONE gate-row-triple (r/z/n rows of this lane's j).
// 24 fma2 per k, over all 8 e-pairs.
// ---------------------------------------------------------------------------
template<int NKQ, int UNROLL>
__device__ __forceinline__ void gates_accum(
    const float* __restrict__ wr, const float* __restrict__ wz,
    const float* __restrict__ wn, const ull* __restrict__ v,
    ull aR[8], ull aZ[8], ull aN[8])
{
    #pragma unroll UNROLL
    for(int kq = 0; kq < NKQ; kq++){
        float4 wr4 = *(const float4*)(wr + kq*4);
        float4 wz4 = *(const float4*)(wz + kq*4);
        float4 wn4 = *(const float4*)(wn + kq*4);
        #pragma unroll
        for(int i = 0; i < 4; i++){
            int k = kq*4 + i;
            const ulonglong2* vp = (const ulonglong2*)(v + k*8);
            ulonglong2 v0 = vp[0], v1 = vp[1], v2 = vp[2], v3 = vp[3];
            float fr = (&wr4.x)[i], fz = (&wz4.x)[i], fn = (&wn4.x)[i];
            ull rp = pack2(fr, fr), zp = pack2(fz, fz), np = pack2(fn, fn);
            aR[0]=fma2(v0.x,rp,aR[0]); aR[1]=fma2(v0.y,rp,aR[1]);
            aR[2]=fma2(v1.x,rp,aR[2]); aR[3]=fma2(v1.y,rp,aR[3]);
            aR[4]=fma2(v2.x,rp,aR[4]); aR[5]=fma2(v2.y,rp,aR[5]);
            aR[6]=fma2(v3.x,rp,aR[6]); aR[7]=fma2(v3.y,rp,aR[7]);
            aZ[0]=fma2(v0.x,zp,aZ[0]); aZ[1]=fma2(v0.y,zp,aZ[1]);
            aZ[2]=fma2(v1.x,zp,aZ[2]); aZ[3]=fma2(v1.y,zp,aZ[3]);
            aZ[4]=fma2(v2.x,zp,aZ[4]); aZ[5]=fma2(v2.y,zp,aZ[5]);
            aZ[6]=fma2(v3.x,zp,aZ[6]); aZ[7]=fma2(v3.y,zp,aZ[7]);
            aN[0]=fma2(v0.x,np,aN[0]); aN[1]=fma2(v0.y,np,aN[1]);
            aN[2]=fma2(v1.x,np,aN[2]); aN[3]=fma2(v1.y,np,aN[3]);
            aN[4]=fma2(v2.x,np,aN[4]); aN[5]=fma2(v2.y,np,aN[5]);
            aN[6]=fma2(v3.x,np,aN[6]); aN[7]=fma2(v3.y,np,aN[7]);
        }
    }
}

// One GRU step: this lane computes h_new[j] for its group's 16 elements.
// Reads h from hcur, writes h_new into hnxt. No sync inside.
__device__ __forceinline__ void gru_step(
    const float* __restrict__ wrih, const float* __restrict__ wzih,
    const float* __restrict__ wnih,
    const float* __restrict__ wrhh, const float* __restrict__ wzhh,
    const float* __restrict__ wnhh,
    const ull* __restrict__ hcur, ull* __restrict__ hnxt,
    const ull* __restrict__ xcur, int j,
    ull br2, ull bz2, ull bni2, ull bnh2)
{
    ull aR[8], aZ[8], aNi[8], aHn[8];
    #pragma unroll
    for(int p = 0; p < 8; p++){
        aR[p]=br2; aZ[p]=bz2; aNi[p]=bni2; aHn[p]=bnh2;
    }
    gates_accum<IN_DIM/4, 4>(wrih, wzih, wnih, xcur, aR, aZ, aNi);
    gates_accum<HH/4,     2>(wrhh, wzhh, wnhh, hcur, aR, aZ, aHn);

    // old h for own row j (8 e-pairs = 16 values)
    const ulonglong2* hp = (const ulonglong2*)(hcur + j*8);
    ulonglong2 o0 = hp[0], o1 = hp[1], o2 = hp[2], o3 = hp[3];
    float hold[16];
    { float2 t;
      t=unpack2(o0.x); hold[0]=t.x;  hold[1]=t.y;
      t=unpack2(o0.y); hold[2]=t.x;  hold[3]=t.y;
      t=unpack2(o1.x); hold[4]=t.x;  hold[5]=t.y;
      t=unpack2(o1.y); hold[6]=t.x;  hold[7]=t.y;
      t=unpack2(o2.x); hold[8]=t.x;  hold[9]=t.y;
      t=unpack2(o2.y); hold[10]=t.x; hold[11]=t.y;
      t=unpack2(o3.x); hold[12]=t.x; hold[13]=t.y;
      t=unpack2(o3.y); hold[14]=t.x; hold[15]=t.y; }

    float hn[16];
    #pragma unroll
    for(int p = 0; p < 8; p++){
        float2 r2  = unpack2(aR[p]),  z2  = unpack2(aZ[p]);
        float2 ni2 = unpack2(aNi[p]), nh2 = unpack2(aHn[p]);
        float r0 = sigm(r2.x), r1 = sigm(r2.y);
        float z0 = sigm(z2.x), z1 = sigm(z2.y);
        float n0 = tanhapx(fmaf(r0, nh2.x, ni2.x));
        float n1 = tanhapx(fmaf(r1, nh2.y, ni2.y));
        hn[2*p]   = fmaf(z0, hold[2*p]   - n0, n0);
        hn[2*p+1] = fmaf(z1, hold[2*p+1] - n1, n1);
    }
    ulonglong2* hw = (ulonglong2*)(hnxt + j*8);
    ulonglong2 s0, s1, s2, s3;
    s0.x = pack2(hn[0],hn[1]);   s0.y = pack2(hn[2],hn[3]);
    s1.x = pack2(hn[4],hn[5]);   s1.y = pack2(hn[6],hn[7]);
    s2.x = pack2(hn[8],hn[9]);   s2.y = pack2(hn[10],hn[11]);
    s3.x = pack2(hn[12],hn[13]); s3.y = pack2(hn[14],hn[15]);
    hw[0] = s0; hw[1] = s1; hw[2] = s2; hw[3] = s3;
}

// ---------------------------------------------------------------------------
// Kernel 1: encoder (128 steps) + decoder (100 steps), 16-elem groups
// ---------------------------------------------------------------------------
__global__ void __launch_bounds__(THREADS1, 1) seq_kernel(
    const float* __restrict__ x,    const float* __restrict__ trg,
    const float* __restrict__ eWih, const float* __restrict__ ebih,
    const float* __restrict__ eWhh, const float* __restrict__ ebhh,
    const float* __restrict__ dWih, const float* __restrict__ dbih,
    const float* __restrict__ dWhh, const float* __restrict__ dbhh,
    const float* __restrict__ outW, const float* __restrict__ outb,
    const float* __restrict__ embW, const float* __restrict__ embb)
{
    extern __shared__ unsigned char smem_raw[];
    Smem& s = *reinterpret_cast<Smem*>(smem_raw);
    const int tid   = threadIdx.x;
    const int wid   = tid >> 5;
    const int lane  = tid & 31;
    const int gr    = wid >> 1;          // group 0..1
    const int sub   = wid & 1;           // row-half within group
    const int tid64 = sub*32 + lane;     // 0..63 within group
    const int j     = tid64;             // this lane's gate row 0..63
    const int groupB = (blockIdx.x*NGROUP + gr)*EPG;   // base batch index

    // ---- stage encoder weights (row-native, padded stride) ----
    for(int i = tid; i < 192*HH; i += THREADS1){
        int r = i >> 6, k = i & 63;
        s.wT[r*WSTRIDE + k] = eWhh[i];
    }
    for(int i = tid; i < 192*IN_DIM; i += THREADS1){
        int r = i >> 4, d = i & 15;
        s.wiT[r*WISTRIDE + d] = eWih[i];
    }
    for(int i = tid; i < 16*HH; i += THREADS1){
        int dd = i >> 6, k = i & 63;
        s.outw[dd*OWSTRIDE + k] = outW[i];
    }

    // weight row pointers for this lane's gate rows (j, 64+j, 128+j)
    const float* wrhh = s.wT + (      j)*WSTRIDE;
    const float* wzhh = s.wT + ( 64 + j)*WSTRIDE;
    const float* wnhh = s.wT + (128 + j)*WSTRIDE;
    const float* wrih = s.wiT + (      j)*WISTRIDE;
    const float* wzih = s.wiT + ( 64 + j)*WISTRIDE;
    const float* wnih = s.wiT + (128 + j)*WISTRIDE;

    // zero h buffer 0
    {
        ull* hb = s.h2[gr][0];
        for(int i = tid64; i < HH*8; i += 64) hb[i] = 0ull;
    }
    __syncthreads();

    // packed encoder biases for row j
    ull br2  = pack2(ebih[j] + ebhh[j],       ebih[j] + ebhh[j]);
    ull bz2  = pack2(ebih[64+j] + ebhh[64+j], ebih[64+j] + ebhh[64+j]);
    ull bni2 = pack2(ebih[128+j], ebih[128+j]);
    ull bnh2 = pack2(ebhh[128+j], ebhh[128+j]);

    // x gather mapping: tid64 -> (elem e, dims d0..d0+3)
    const int e  = tid64 >> 2;           // 0..15
    const int d0 = (tid64 & 3) * 4;      // 0,4,8,12
    const float* xbase = x + ((size_t)(groupB + e)*SRC_LEN)*IN_DIM + d0;

    // preload x[0] into buf 0
    {
        float4 xv = *(const float4*)xbase;
        float* xf0 = (float*)s.x2[gr][0];
        xf0[(d0+0)*16 + e] = xv.x;
        xf0[(d0+1)*16 + e] = xv.y;
        xf0[(d0+2)*16 + e] = xv.z;
        xf0[(d0+3)*16 + e] = xv.w;
    }
    PBAR(gr);

    int cur = 0;

    // ================= encoder =================
    for(int t = 0; t < SRC_LEN; t++){
        int nxt = cur ^ 1;
        if(t + 1 < SRC_LEN){
            float4 xv = *(const float4*)(xbase + (size_t)(t+1)*IN_DIM);
            float* xfn = (float*)s.x2[gr][nxt];
            xfn[(d0+0)*16 + e] = xv.x;
            xfn[(d0+1)*16 + e] = xv.y;
            xfn[(d0+2)*16 + e] = xv.z;
            xfn[(d0+3)*16 + e] = xv.w;
        }
        gru_step(wrih, wzih, wnih, wrhh, wzhh, wnhh,
                 s.h2[gr][cur], s.h2[gr][nxt], s.x2[gr][cur], j,
                 br2, bz2, bni2, bnh2);
        PBAR(gr);
        cur = nxt;
    }
    // cur == 0 again (128 flips), final encoder h in h2[gr][0]

    // ---- switch to decoder weights ----
    __syncthreads();
    for(int i = tid; i < 192*HH; i += THREADS1){
        int r = i >> 6, k = i & 63;
        s.wT[r*WSTRIDE + k] = dWhh[i];
    }
    for(int i = tid; i < 192*IN_DIM; i += THREADS1){
        int r = i >> 4, d = i & 15;
        s.wiT[r*WISTRIDE + d] = dWih[i];
    }

    // decoder biases
    br2  = pack2(dbih[j] + dbhh[j],       dbih[j] + dbhh[j]);
    bz2  = pack2(dbih[64+j] + dbhh[64+j], dbih[64+j] + dbhh[64+j]);
    bni2 = pack2(dbih[128+j], dbih[128+j]);
    bnh2 = pack2(dbhh[128+j], dbhh[128+j]);

    // initial decoder input: emb(trg) -> x buf 0
    {
        float4 tv = *(const float4*)(trg + (size_t)(groupB + e)*4);
        float* xf0 = (float*)s.x2[gr][0];
        #pragma unroll
        for(int i = 0; i < 4; i++){
            int d = d0 + i;
            float a = embb[d] + embW[d*4+0]*tv.x + embW[d*4+1]*tv.y
                              + embW[d*4+2]*tv.z + embW[d*4+3]*tv.w;
            xf0[d*16 + e] = a;
        }
    }

    // out-proj mapping: tid64 -> (out dim dd, quad oq); lane does e-pairs
    // 2*oq, 2*oq+1 (elements 4*oq .. 4*oq+3)
    const int dd = tid64 >> 2;          // 0..15
    const int oq = tid64 & 3;           // 0..3
    const float ob = outb[dd];
    const float* owrow = s.outw + dd*OWSTRIDE;
    __syncthreads();

    // ================= decoder =================
    for(int t = 0; t < SEQ_LEN; t++){
        int nxt = cur ^ 1;
        gru_step(wrih, wzih, wnih, wrhh, wzhh, wnhh,
                 s.h2[gr][cur], s.h2[gr][nxt], s.x2[gr][cur], j,
                 br2, bz2, bni2, bnh2);
        PBAR(gr);    // h_new complete (both halves)

        // out projection: o[dd] for e-pairs 2oq, 2oq+1 (4 elements)
        const ull* hnew = s.h2[gr][nxt];
        ull oA = pack2(ob, ob), oB = pack2(ob, ob);
        #pragma unroll 4
        for(int kq = 0; kq < 16; kq++){
            float4 w4 = *(const float4*)(owrow + kq*4);
            #pragma unroll
            for(int i = 0; i < 4; i++){
                int k = kq*4 + i;
                ulonglong2 hp = *(const ulonglong2*)(hnew + k*8 + oq*2);
                float wv = (&w4.x)[i];
                ull wp = pack2(wv, wv);
                oA = fma2(hp.x, wp, oA);
                oB = fma2(hp.y, wp, oB);
            }
        }
        // feed back as next x + store to g_dec
        s.x2[gr][nxt][dd*8 + oq*2]     = oA;
        s.x2[gr][nxt][dd*8 + oq*2 + 1] = oB;
        float2 fa = unpack2(oA), fb = unpack2(oB);
        int b0 = groupB + 4*oq;
        size_t gb = ((size_t)b0*SEQ_LEN + t)*IN_DIM + dd;
        const size_t ES = (size_t)SEQ_LEN*IN_DIM;
        g_dec[gb]        = fa.x;
        g_dec[gb + ES]   = fa.y;
        g_dec[gb + 2*ES] = fb.x;
        g_dec[gb + 3*ES] = fb.y;
        PBAR(gr);    // x_next complete
        cur = nxt;
    }
}

// ---------------------------------------------------------------------------
// A&S 7.1.26 erf-based exact GELU (|erf err| <= 1.5e-7)
// ---------------------------------------------------------------------------
__device__ __forceinline__ float gelu_exact(float x){
    const float A1 =  0.254829592f, A2 = -0.284496736f, A3 = 1.421413741f;
    const float A4 = -1.453152027f, A5 =  1.061405429f, P  = 0.3275911f;
    float sarg = 0.70710678118654752f * x;
    float a = fabsf(sarg);
    float t = __fdividef(1.f, fmaf(P, a, 1.f));
    float poly = t*fmaf(t, fmaf(t, fmaf(t, fmaf(t, A5, A4), A3), A2), A1);
    float erf = fmaf(-poly, __expf(-a*a), 1.f);
    erf = copysignf(erf, sarg);
    return 0.5f * x * (1.f + erf);
}

// ---------------------------------------------------------------------------
// Kernel 2: output heads, 2 rows per thread, f32x2
// ---------------------------------------------------------------------------
__global__ void __launch_bounds__(256) heads_kernel(
    const float* __restrict__ mhW1, const float* __restrict__ mhb1,
    const float* __restrict__ mhW2, const float* __restrict__ mhb2,
    const float* __restrict__ chW1, const float* __restrict__ chb1,
    const float* __restrict__ chW2, const float* __restrict__ chb2,
    float* __restrict__ out)
{
    __shared__ __align__(16) float w1m[HH*IN_DIM], w1c[HH*IN_DIM];
    __shared__ __align__(16) ull  w2mP[HH*2];
    __shared__ __align__(16) ull  w2cP[HH*5];
    __shared__ float b1m[HH], b1c[HH];
    __shared__ float b2m[MEAN_DIM], b2c[COV_DIM];

    int tid = threadIdx.x;
    for(int i = tid; i < HH*IN_DIM; i += 256){ w1m[i] = mhW1[i]; w1c[i] = chW1[i]; }
    for(int i = tid; i < HH*2; i += 256){
        int u = i >> 1, mp = i & 1;
        w2mP[i] = pack2(mhW2[(2*mp)*HH + u], mhW2[(2*mp+1)*HH + u]);
    }
    for(int i = tid; i < HH*5; i += 256){
        int u = i / 5, vp = i - u*5;
        w2cP[i] = pack2(chW2[(2*vp)*HH + u], chW2[(2*vp+1)*HH + u]);
    }
    if(tid < HH){ b1m[tid] = mhb1[tid]; b1c[tid] = chb1[tid]; }
    if(tid < MEAN_DIM) b2m[tid] = mhb2[tid];
    if(tid < COV_DIM)  b2c[tid] = chb2[tid];
    __syncthreads();

    int r0 = (blockIdx.x*256 + tid)*2;      // rows r0, r0+1
    const ulonglong2* opA = (const ulonglong2*)&g_dec[(size_t)r0*IN_DIM];
    ulonglong2 qa0 = opA[0], qa1 = opA[1], qa2 = opA[2], qa3 = opA[3];
    ulonglong2 qb0 = opA[4], qb1 = opA[5], qb2 = opA[6], qb3 = opA[7];
    ull ovA[8] = { qa0.x,qa0.y,qa1.x,qa1.y,qa2.x,qa2.y,qa3.x,qa3.y };
    ull ovB[8] = { qb0.x,qb0.y,qb1.x,qb1.y,qb2.x,qb2.y,qb3.x,qb3.y };

    ull amA[2], amB[2], acA[5], acB[5];
    amA[0] = amB[0] = pack2(b2m[0], b2m[1]);
    amA[1] = amB[1] = pack2(b2m[2], b2m[3]);
    #pragma unroll
    for(int vp = 0; vp < 5; vp++) acA[vp] = acB[vp] = pack2(b2c[2*vp], b2c[2*vp+1]);

    #pragma unroll 4
    for(int u = 0; u < HH; u++){
        const ull* w1mp = (const ull*)(w1m + u*16);
        const ull* w1cp = (const ull*)(w1c + u*16);
        ull a1A = 0, a1B = 0, a2A = 0, a2B = 0;
        #pragma unroll
        for(int i = 0; i < 8; i++){
            ull wm = w1mp[i], wc = w1cp[i];
            a1A = fma2(ovA[i], wm, a1A);
            a1B = fma2(ovB[i], wm, a1B);
            a2A = fma2(ovA[i], wc, a2A);
            a2B = fma2(ovB[i], wc, a2B);
        }
        float2 f;
        f = unpack2(a1A); float s1A = b1m[u] + f.x + f.y;
        f = unpack2(a1B); float s1B = b1m[u] + f.x + f.y;
        f = unpack2(a2A); float s2A = b1c[u] + f.x + f.y;
        f = unpack2(a2B); float s2B = b1c[u] + f.x + f.y;
        float g1A = gelu_exact(s1A), g1B = gelu_exact(s1B);
        float g2A = gelu_exact(s2A), g2B = gelu_exact(s2B);
        ull g1Ap = pack2(g1A, g1A), g1Bp = pack2(g1B, g1B);
        ull g2Ap = pack2(g2A, g2A), g2Bp = pack2(g2B, g2B);
        ull wm0 = w2mP[u*2], wm1 = w2mP[u*2+1];
        amA[0] = fma2(g1Ap, wm0, amA[0]); amA[1] = fma2(g1Ap, wm1, amA[1]);
        amB[0] = fma2(g1Bp, wm0, amB[0]); amB[1] = fma2(g1Bp, wm1, amB[1]);
        #pragma unroll
        for(int vp = 0; vp < 5; vp++){
            ull wcv = w2cP[u*5+vp];
            acA[vp] = fma2(g2Ap, wcv, acA[vp]);
            acB[vp] = fma2(g2Bp, wcv, acB[vp]);
        }
    }

    // clamp means dims 2,3 to [-1,1]
    { float2 m = unpack2(amA[1]);
      m.x = fminf(fmaxf(m.x, -1.f), 1.f); m.y = fminf(fmaxf(m.y, -1.f), 1.f);
      amA[1] = pack2(m.x, m.y); }
    { float2 m = unpack2(amB[1]);
      m.x = fminf(fmaxf(m.x, -1.f), 1.f); m.y = fminf(fmaxf(m.y, -1.f), 1.f);
      amB[1] = pack2(m.x, m.y); }

    ull* om = (ull*)(out + MEANS_OFF) + (size_t)r0*2;
    om[0] = amA[0]; om[1] = amA[1]; om[2] = amB[0]; om[3] = amB[1];
    ull* oc = (ull*)(out + COVS_OFF) + (size_t)r0*5;
    #pragma unroll
    for(int vp = 0; vp < 5; vp++){ oc[vp] = acA[vp]; oc[5+vp] = acB[vp]; }
}

// ---------------------------------------------------------------------------
extern "C" void kernel_launch(void* const* d_in, const int* in_sizes, int n_in,
                              void* d_out, int out_size)
{
    const float* x     = (const float*)d_in[0];
    const float* trg   = (const float*)d_in[1];
    const float* eWih  = (const float*)d_in[2];
    const float* ebih  = (const float*)d_in[3];
    const float* eWhh  = (const float*)d_in[4];
    const float* ebhh  = (const float*)d_in[5];
    const float* dWih  = (const float*)d_in[6];
    const float* dbih  = (const float*)d_in[7];
    const float* dWhh  = (const float*)d_in[8];
    const float* dbhh  = (const float*)d_in[9];
    const float* outW  = (const float*)d_in[10];
    const float* outb  = (const float*)d_in[11];
    const float* embW  = (const float*)d_in[12];
    const float* embb  = (const float*)d_in[13];
    const float* mhW1  = (const float*)d_in[14];
    const float* mhb1  = (const float*)d_in[15];
    const float* mhW2  = (const float*)d_in[16];
    const float* mhb2  = (const float*)d_in[17];
    const float* chW1  = (const float*)d_in[18];
    const float* chb1  = (const float*)d_in[19];
    const float* chW2  = (const float*)d_in[20];
    const float* chb2  = (const float*)d_in[21];

    cudaFuncSetAttribute(seq_kernel, cudaFuncAttributeMaxDynamicSharedMemorySize,
                         (int)sizeof(Smem));

    seq_kernel<<<GRID1, THREADS1, sizeof(Smem)>>>(
        x, trg, eWih, ebih, eWhh, ebhh, dWih, dbih, dWhh, dbhh,
        outW, outb, embW, embb);

    heads_kernel<<<(BB*SEQ_LEN)/512, 256>>>(
        mhW1, mhb1, mhW2, mhb2, chW1, chb1, chW2, chb2, (float*)d_out);
}